// round 10
// baseline (speedup 1.0000x reference)
#include <cuda_runtime.h>
#include <math.h>

#define ETA 0.1f
#define THETA 4.0f
#define NN 4096            // 64*64
#define MATS_PER_CTA 3
#define THREADS 192        // 3 matrices per CTA, 64 threads each
#define MAX_BATCH 8192

typedef unsigned long long u64;

// global scratch: E1 (= scaled A) and A3 per matrix
__device__ float g_scrA [(size_t)MAX_BATCH * NN];
__device__ float g_scrA3[(size_t)MAX_BATCH * NN];

__device__ __forceinline__ u64 fma2(u64 a, u64 b, u64 c) {
    u64 d;
    asm("fma.rn.f32x2 %0, %1, %2, %3;" : "=l"(d) : "l"(a), "l"(b), "l"(c));
    return d;
}
__device__ __forceinline__ u64 dup2(float a) {
    u64 d;
    asm("mov.b64 %0, {%1, %1};" : "=l"(d) : "f"(a));
    return d;
}
__device__ __forceinline__ float2 unpk(u64 v) {
    float2 r;
    asm("mov.b64 {%0, %1}, %2;" : "=f"(r.x), "=f"(r.y) : "l"(v));
    return r;
}

// per-matrix barrier (64 threads = 2 warps), compile-time immediate id
__device__ __forceinline__ void hbar(int m) {
    if (m == 0)      asm volatile("bar.sync 1, 64;" ::: "memory");
    else if (m == 1) asm volatile("bar.sync 2, 64;" ::: "memory");
    else             asm volatile("bar.sync 3, 64;" ::: "memory");
}

// swizzled float offset of logical (row, float4-chunk). chunk in [0,16).
__device__ __forceinline__ int sw(int r, int c) {
    return (r << 6) + ((c ^ ((r >> 2) & 6)) << 2);
}

__global__ void __launch_bounds__(THREADS, 1)
meg_update_kernel(const float* __restrict__ gR,
                  const float* __restrict__ gG,
                  float* __restrict__ gOut, int batch) {
    const int tid = threadIdx.x;
    const int m = tid >> 6;          // which matrix of this CTA
    const int t = tid & 63;

    const int gmat = blockIdx.x * MATS_PER_CTA + m;
    if (gmat >= batch) return;       // tail CTA: whole warp-pair exits

    extern __shared__ float smx[];
    float* s0 = smx + m * 4 * NN;    // A, later S2 ping-pong
    float* s1 = s0 + 1 * NN;         // A2 (and E2)
    float* s2 = s0 + 2 * NN;         // A4
    float* s3 = s0 + 3 * NN;         // S ping-pong

    float* gE1 = g_scrA  + (size_t)gmat * NN;   // scaled A
    float* gE3 = g_scrA3 + (size_t)gmat * NN;   // A3

    __shared__ float s_red[MATS_PER_CTA][2];
    __shared__ int   s_nsq[MATS_PER_CTA];

    const size_t gbase = (size_t)gmat * NN;
    const float4* R4 = (const float4*)(gR + gbase);
    const float4* G4 = (const float4*)(gG + gbase);
    float4* O4 = (float4*)(gOut + gbase);

    // ---- load G (swizzled) into s3 ----
#pragma unroll
    for (int q = 0; q < 16; q++) {
        const int e4 = t + q * 64;
        const int r = e4 >> 4, c4 = e4 & 15;
        *(float4*)(s3 + sw(r, c4)) = G4[e4];
    }
    hbar(m);

    // ---- A = log(R) - ETA*(G - G^T) -> s0 ----
#pragma unroll
    for (int q = 0; q < 16; q++) {
        const int e4 = t + q * 64;
        const int r = e4 >> 4, c4 = e4 & 15;
        const int cb = c4 << 2;
        const float4 rv = R4[e4];
        const float4 gv = *(const float4*)(s3 + sw(r, c4));
        const float gt0 = s3[sw(cb + 0, r >> 2) + (r & 3)];
        const float gt1 = s3[sw(cb + 1, r >> 2) + (r & 3)];
        const float gt2 = s3[sw(cb + 2, r >> 2) + (r & 3)];
        const float gt3 = s3[sw(cb + 3, r >> 2) + (r & 3)];
        float4 a;
        a.x = logf(rv.x) - ETA * (gv.x - gt0);
        a.y = logf(rv.y) - ETA * (gv.y - gt1);
        a.z = logf(rv.z) - ETA * (gv.z - gt2);
        a.w = logf(rv.w) - ETA * (gv.w - gt3);
        *(float4*)(s0 + sw(r, c4)) = a;
    }
    hbar(m);

    // ---- inf-norm: thread t owns row t ----
    {
        float rs = 0.0f;
#pragma unroll
        for (int c = 0; c < 16; c++) {
            const float4 v = *(const float4*)(s0 + sw(t, c));
            rs += fabsf(v.x) + fabsf(v.y) + fabsf(v.z) + fabsf(v.w);
        }
#pragma unroll
        for (int o = 16; o > 0; o >>= 1)
            rs = fmaxf(rs, __shfl_xor_sync(0xffffffffu, rs, o));
        if ((t & 31) == 0) s_red[m][t >> 5] = rs;
        hbar(m);
        if (t == 0) {
            const float nrm = fmaxf(s_red[m][0], s_red[m][1]);
            int s = 0;
            if (nrm > THETA && isfinite(nrm)) {
                s = (int)ceilf(log2f(nrm / THETA));
                if (s < 0) s = 0;
                if (s > 30) s = 30;
            }
            s_nsq[m] = s;
        }
        hbar(m);
    }
    const int nsq = s_nsq[m];
    const float scale = exp2f((float)-nsq);

    // ---- scale A in s0; also persist scaled A to global (E1) ----
#pragma unroll
    for (int q = 0; q < 16; q++) {
        float4* p = (float4*)s0 + (t + q * 64);
        float4 v = *p;
        v.x *= scale; v.y *= scale; v.z *= scale; v.w *= scale;
        *p = v;
        ((float4*)gE1)[t + q * 64] = v;   // same swizzled layout in global
    }
    __threadfence_block();
    hbar(m);

    // Taylor 1/k! coefficients
    const float c0  = 1.0f, c1 = 1.0f, c2 = 0.5f;
    const float c3  = (float)(1.0 / 6.0),            c4c = (float)(1.0 / 24.0);
    const float c5  = (float)(1.0 / 120.0),          c6 = (float)(1.0 / 720.0);
    const float c7  = (float)(1.0 / 5040.0),         c8 = (float)(1.0 / 40320.0);
    const float c9  = (float)(1.0 / 362880.0),       c10 = (float)(1.0 / 3628800.0);
    const float c11 = (float)(1.0 / 39916800.0),     c12 = (float)(1.0 / 479001600.0);
    const float c13 = (float)(1.0 / 6227020800.0),   c14 = (float)(1.0 / 87178291200.0);
    const float c15 = (float)(1.0 / 1307674368000.0);
    const float c16 = (float)(1.0 / 20922789888000.0);

    // ---- unified GEMM step loop ----
    const int ty = t >> 3, tx = t & 7;
    const int r0 = ty << 3;
    const int sA = (ty & 3) << 1;
    const int sc = tx ^ sA;

    const int nsteps = 6 + nsq;
#pragma unroll 1
    for (int step = 0; step < nsteps; step++) {
        // --- pointer / coefficient selection (uniform) ---
        float* C; const float* A; const float* B;
        float d0 = 0.f, d1 = 0.f, d2 = 0.f, d3 = 0.f;
        bool epi = false, toGlobal = false;
        if (step == 0)      { C = s1; A = s0; B = s0; }            // A2
        else if (step == 1) { C = s1; A = s1; B = s0; toGlobal = true; }  // A3 -> global
        else if (step == 2) { C = s2; A = s1; B = s1; }            // A4
        else if (step < 6) {
            const int h = step - 3;
            A = s2;
            if (h == 1) { B = s0; C = s3; }
            else        { B = s3; C = s0; }
            epi = true;
            d0 = (h == 0) ? c8  : (h == 1) ? c4c : c0;
            d1 = (h == 0) ? c9  : (h == 1) ? c5  : c1;
            d2 = (h == 0) ? c10 : (h == 1) ? c6  : c2;
            d3 = (h == 0) ? c11 : (h == 1) ? c7  : c3;
        } else {
            if (((step - 6) & 1) == 0) { A = s0; B = s0; C = s3; }
            else                       { A = s3; B = s3; C = s0; }
        }

        // --- seed S (-> s3) after powers are ready, before first Horner ---
        if (step == 3) {
#pragma unroll
            for (int q = 0; q < 16; q++) {
                const int e4 = t + q * 64;
                const int r = e4 >> 4, c4 = e4 & 15;
                const int off = sw(r, c4);
                const float4 a  = *(const float4*)(s0 + off);
                const float4 a2 = *(const float4*)(s1 + off);
                const float4 a3 = ((const float4*)gE3)[e4];
                const float4 a4 = *(const float4*)(s2 + off);
                float4 s;
                s.x = fmaf(c13, a.x, fmaf(c14, a2.x, fmaf(c15, a3.x, c16 * a4.x)));
                s.y = fmaf(c13, a.y, fmaf(c14, a2.y, fmaf(c15, a3.y, c16 * a4.y)));
                s.z = fmaf(c13, a.z, fmaf(c14, a2.z, fmaf(c15, a3.z, c16 * a4.z)));
                s.w = fmaf(c13, a.w, fmaf(c14, a2.w, fmaf(c15, a3.w, c16 * a4.w)));
                if ((r >> 2) == c4) ((float*)&s)[r & 3] += c12;
                *(float4*)(s3 + off) = s;
            }
            hbar(m);
        }

        // --- the single GEMM instance ---
        u64 acc[8][4];
#pragma unroll
        for (int i = 0; i < 8; i++) { acc[i][0] = acc[i][1] = acc[i][2] = acc[i][3] = 0ull; }

        float4 av[2][8];
        ulonglong2 bv[2][2];

#define AVLOAD(buf, cc) do {                                                       \
        const int ao_ = (((cc) ^ sA) << 2);                                        \
        _Pragma("unroll")                                                          \
        for (int i_ = 0; i_ < 8; i_++)                                             \
            av[buf][i_] = *(const float4*)(A + ((r0 + i_) << 6) + ao_);            \
    } while (0)

#define BVLOAD(buf, K) do {                                                        \
        const int kr_ = (K) < 63 ? (K) : 63;                                       \
        const int bo_ = ((tx ^ ((kr_ >> 2) & 6)) << 2);                            \
        const float* br_ = B + (kr_ << 6);                                         \
        bv[buf][0] = *(const ulonglong2*)(br_ + bo_);                              \
        bv[buf][1] = *(const ulonglong2*)(br_ + bo_ + 32);                         \
    } while (0)

#define MMCOMP(ab, bb, kk) do {                                                    \
        _Pragma("unroll")                                                          \
        for (int i_ = 0; i_ < 8; i_++) {                                           \
            const float a_ = ((const float*)&av[ab][i_])[kk];                      \
            const u64 aa_ = dup2(a_);                                              \
            acc[i_][0] = fma2(aa_, bv[bb][0].x, acc[i_][0]);                       \
            acc[i_][1] = fma2(aa_, bv[bb][0].y, acc[i_][1]);                       \
            acc[i_][2] = fma2(aa_, bv[bb][1].x, acc[i_][2]);                       \
            acc[i_][3] = fma2(aa_, bv[bb][1].y, acc[i_][3]);                       \
        }                                                                          \
    } while (0)

#define CHUNK(ab, Kbase) do {                                                      \
        BVLOAD(1, (Kbase) + 1); MMCOMP(ab, 0, 0);                                  \
        BVLOAD(0, (Kbase) + 2); MMCOMP(ab, 1, 1);                                  \
        BVLOAD(1, (Kbase) + 3); MMCOMP(ab, 0, 2);                                  \
        BVLOAD(0, (Kbase) + 4); MMCOMP(ab, 1, 3);                                  \
    } while (0)

        AVLOAD(0, 0);
        BVLOAD(0, 0);
#pragma unroll 1
        for (int b = 0; b < 8; b++) {
            const int cc = 2 * b;
            AVLOAD(1, cc + 1);
            CHUNK(0, cc * 4);
            const int nc = (cc + 2 < 15) ? (cc + 2) : 15;
            AVLOAD(0, nc);
            CHUNK(1, (cc + 1) * 4);
        }

#undef AVLOAD
#undef BVLOAD
#undef MMCOMP
#undef CHUNK

        // --- epilogue + store ---
#pragma unroll
        for (int i = 0; i < 8; i++) {
            const int row = r0 + i;
            const int offL = (row << 6) + (sc << 2);
            const int offH = offL + 32;
            const float2 p0 = unpk(acc[i][0]), p1 = unpk(acc[i][1]);
            const float2 p2 = unpk(acc[i][2]), p3 = unpk(acc[i][3]);
            float4 o0 = make_float4(p0.x, p0.y, p1.x, p1.y);
            float4 o1 = make_float4(p2.x, p2.y, p3.x, p3.y);
            if (epi) {
                const float4 e1L = *(const float4*)(gE1 + offL);   // global
                const float4 e2L = *(const float4*)(s1  + offL);   // smem
                const float4 e3L = *(const float4*)(gE3 + offL);   // global
                const float4 e1H = *(const float4*)(gE1 + offH);
                const float4 e2H = *(const float4*)(s1  + offH);
                const float4 e3H = *(const float4*)(gE3 + offH);
                o0.x += fmaf(d1, e1L.x, fmaf(d2, e2L.x, d3 * e3L.x));
                o0.y += fmaf(d1, e1L.y, fmaf(d2, e2L.y, d3 * e3L.y));
                o0.z += fmaf(d1, e1L.z, fmaf(d2, e2L.z, d3 * e3L.z));
                o0.w += fmaf(d1, e1L.w, fmaf(d2, e2L.w, d3 * e3L.w));
                o1.x += fmaf(d1, e1H.x, fmaf(d2, e2H.x, d3 * e3H.x));
                o1.y += fmaf(d1, e1H.y, fmaf(d2, e2H.y, d3 * e3H.y));
                o1.z += fmaf(d1, e1H.z, fmaf(d2, e2H.z, d3 * e3H.z));
                o1.w += fmaf(d1, e1H.w, fmaf(d2, e2H.w, d3 * e3H.w));
                if ((row >> 2) == tx)     ((float*)&o0)[i & 3] += d0;
                if ((row >> 2) == tx + 8) ((float*)&o1)[i & 3] += d0;
            }
            if (toGlobal) {
                *(float4*)(gE3 + offL) = o0;
                *(float4*)(gE3 + offH) = o1;
            } else {
                *(float4*)(C + offL) = o0;
                *(float4*)(C + offH) = o1;
            }
        }
        if (toGlobal) __threadfence_block();
        hbar(m);
    }

    // ---- store (de-swizzle): result in s0 if nsq even, else s3 ----
    const float* src = (nsq & 1) ? s3 : s0;
#pragma unroll
    for (int q = 0; q < 16; q++) {
        const int e4 = t + q * 64;
        const int r = e4 >> 4, c4 = e4 & 15;
        O4[e4] = *(const float4*)(src + sw(r, c4));
    }
}

extern "C" void kernel_launch(void* const* d_in, const int* in_sizes, int n_in,
                              void* d_out, int out_size) {
    const float* R = (const float*)d_in[0];
    const float* G = (const float*)d_in[1];
    float* out = (float*)d_out;

    const int batch = in_sizes[0] / NN;                              // 8192
    const int grid = (batch + MATS_PER_CTA - 1) / MATS_PER_CTA;      // 2731
    const size_t smem = MATS_PER_CTA * 4 * NN * sizeof(float);       // 192 KB

    static bool attr_set = false;
    if (!attr_set) {
        cudaFuncSetAttribute(meg_update_kernel,
                             cudaFuncAttributeMaxDynamicSharedMemorySize,
                             (int)smem);
        attr_set = true;
    }

    meg_update_kernel<<<grid, THREADS, smem>>>(R, G, out, batch);
}

// round 11
// speedup vs baseline: 1.0497x; 1.0497x over previous
#include <cuda_runtime.h>
#include <math.h>

#define ETA 0.1f
#define THETA 4.0f
#define NN 4096            // 64*64
#define MATS_PER_CTA 3
#define THREADS 192        // 3 matrices per CTA, 64 threads each
#define MAX_BATCH 8192

typedef unsigned long long u64;

// global scratch: E1 (= scaled A) and A3 per matrix
__device__ float g_scrA [(size_t)MAX_BATCH * NN];
__device__ float g_scrA3[(size_t)MAX_BATCH * NN];

__device__ __forceinline__ u64 fma2(u64 a, u64 b, u64 c) {
    u64 d;
    asm("fma.rn.f32x2 %0, %1, %2, %3;" : "=l"(d) : "l"(a), "l"(b), "l"(c));
    return d;
}
__device__ __forceinline__ u64 dup2(float a) {
    u64 d;
    asm("mov.b64 %0, {%1, %1};" : "=l"(d) : "f"(a));
    return d;
}
__device__ __forceinline__ float2 unpk(u64 v) {
    float2 r;
    asm("mov.b64 {%0, %1}, %2;" : "=f"(r.x), "=f"(r.y) : "l"(v));
    return r;
}

// per-matrix barrier (64 threads = 2 warps), compile-time immediate id
__device__ __forceinline__ void hbar(int m) {
    if (m == 0)      asm volatile("bar.sync 1, 64;" ::: "memory");
    else if (m == 1) asm volatile("bar.sync 2, 64;" ::: "memory");
    else             asm volatile("bar.sync 3, 64;" ::: "memory");
}

// swizzled float offset of logical (row, float4-chunk). chunk in [0,16).
__device__ __forceinline__ int sw(int r, int c) {
    return (r << 6) + ((c ^ ((r >> 2) & 6)) << 2);
}

__global__ void __launch_bounds__(THREADS, 1)
meg_update_kernel(const float* __restrict__ gR,
                  const float* __restrict__ gG,
                  float* __restrict__ gOut, int batch) {
    const int tid = threadIdx.x;
    const int m = tid >> 6;          // which matrix of this CTA
    const int t = tid & 63;

    const int gmat = blockIdx.x * MATS_PER_CTA + m;
    if (gmat >= batch) return;       // tail CTA: whole warp-pair exits

    extern __shared__ float smx[];
    float* s0 = smx + m * 4 * NN;    // A, later S2 ping-pong
    float* s1 = s0 + 1 * NN;         // A2 (and E2)
    float* s2 = s0 + 2 * NN;         // A4
    float* s3 = s0 + 3 * NN;         // S ping-pong

    float* gE1 = g_scrA  + (size_t)gmat * NN;   // scaled A
    float* gE3 = g_scrA3 + (size_t)gmat * NN;   // A3

    __shared__ float s_red[MATS_PER_CTA][2];
    __shared__ int   s_nsq[MATS_PER_CTA];

    const size_t gbase = (size_t)gmat * NN;
    const float4* R4 = (const float4*)(gR + gbase);
    const float4* G4 = (const float4*)(gG + gbase);
    float4* O4 = (float4*)(gOut + gbase);

    // ---- load G (swizzled) into s3 ----
#pragma unroll
    for (int q = 0; q < 16; q++) {
        const int e4 = t + q * 64;
        const int r = e4 >> 4, c4 = e4 & 15;
        *(float4*)(s3 + sw(r, c4)) = G4[e4];
    }
    hbar(m);

    // ---- A = log(R) - ETA*(G - G^T) -> s0 ----
#pragma unroll
    for (int q = 0; q < 16; q++) {
        const int e4 = t + q * 64;
        const int r = e4 >> 4, c4 = e4 & 15;
        const int cb = c4 << 2;
        const float4 rv = R4[e4];
        const float4 gv = *(const float4*)(s3 + sw(r, c4));
        const float gt0 = s3[sw(cb + 0, r >> 2) + (r & 3)];
        const float gt1 = s3[sw(cb + 1, r >> 2) + (r & 3)];
        const float gt2 = s3[sw(cb + 2, r >> 2) + (r & 3)];
        const float gt3 = s3[sw(cb + 3, r >> 2) + (r & 3)];
        float4 a;
        a.x = logf(rv.x) - ETA * (gv.x - gt0);
        a.y = logf(rv.y) - ETA * (gv.y - gt1);
        a.z = logf(rv.z) - ETA * (gv.z - gt2);
        a.w = logf(rv.w) - ETA * (gv.w - gt3);
        *(float4*)(s0 + sw(r, c4)) = a;
    }
    hbar(m);

    // ---- inf-norm: thread t owns row t ----
    {
        float rs = 0.0f;
#pragma unroll
        for (int c = 0; c < 16; c++) {
            const float4 v = *(const float4*)(s0 + sw(t, c));
            rs += fabsf(v.x) + fabsf(v.y) + fabsf(v.z) + fabsf(v.w);
        }
#pragma unroll
        for (int o = 16; o > 0; o >>= 1)
            rs = fmaxf(rs, __shfl_xor_sync(0xffffffffu, rs, o));
        if ((t & 31) == 0) s_red[m][t >> 5] = rs;
        hbar(m);
        if (t == 0) {
            const float nrm = fmaxf(s_red[m][0], s_red[m][1]);
            int s = 0;
            if (nrm > THETA && isfinite(nrm)) {
                s = (int)ceilf(log2f(nrm / THETA));
                if (s < 0) s = 0;
                if (s > 30) s = 30;
            }
            s_nsq[m] = s;
        }
        hbar(m);
    }
    const int nsq = s_nsq[m];
    const float scale = exp2f((float)-nsq);

    // ---- scale A in s0; also persist scaled A to global (E1) ----
#pragma unroll
    for (int q = 0; q < 16; q++) {
        float4* p = (float4*)s0 + (t + q * 64);
        float4 v = *p;
        v.x *= scale; v.y *= scale; v.z *= scale; v.w *= scale;
        *p = v;
        ((float4*)gE1)[t + q * 64] = v;   // same swizzled layout in global
    }
    __threadfence_block();
    hbar(m);

    // Taylor 1/k! coefficients
    const float c0  = 1.0f, c1 = 1.0f, c2 = 0.5f;
    const float c3  = (float)(1.0 / 6.0),            c4c = (float)(1.0 / 24.0);
    const float c5  = (float)(1.0 / 120.0),          c6 = (float)(1.0 / 720.0);
    const float c7  = (float)(1.0 / 5040.0),         c8 = (float)(1.0 / 40320.0);
    const float c9  = (float)(1.0 / 362880.0),       c10 = (float)(1.0 / 3628800.0);
    const float c11 = (float)(1.0 / 39916800.0),     c12 = (float)(1.0 / 479001600.0);
    const float c13 = (float)(1.0 / 6227020800.0),   c14 = (float)(1.0 / 87178291200.0);
    const float c15 = (float)(1.0 / 1307674368000.0);
    const float c16 = (float)(1.0 / 20922789888000.0);

    // ---- unified GEMM step loop ----
    const int ty = t >> 3, tx = t & 7;
    const int r0 = ty << 3;
    const int sA = (ty & 3) << 1;
    const int sc = tx ^ sA;

    const int nsteps = 6 + nsq;
#pragma unroll 1
    for (int step = 0; step < nsteps; step++) {
        // --- pointer / coefficient selection (uniform) ---
        float* C; const float* A; const float* B;
        float d0 = 0.f, d1 = 0.f, d2 = 0.f, d3 = 0.f;
        bool epi = false, toGlobal = false;
        if (step == 0)      { C = s1; A = s0; B = s0; }            // A2
        else if (step == 1) { C = s1; A = s1; B = s0; toGlobal = true; }  // A3 -> global
        else if (step == 2) { C = s2; A = s1; B = s1; }            // A4
        else if (step < 6) {
            const int h = step - 3;
            A = s2;
            if (h == 1) { B = s0; C = s3; }
            else        { B = s3; C = s0; }
            epi = true;
            d0 = (h == 0) ? c8  : (h == 1) ? c4c : c0;
            d1 = (h == 0) ? c9  : (h == 1) ? c5  : c1;
            d2 = (h == 0) ? c10 : (h == 1) ? c6  : c2;
            d3 = (h == 0) ? c11 : (h == 1) ? c7  : c3;
        } else {
            if (((step - 6) & 1) == 0) { A = s0; B = s0; C = s3; }
            else                       { A = s3; B = s3; C = s0; }
        }

        // --- seed S (-> s3) after powers are ready, before first Horner ---
        if (step == 3) {
#pragma unroll
            for (int q = 0; q < 16; q++) {
                const int e4 = t + q * 64;
                const int r = e4 >> 4, c4 = e4 & 15;
                const int off = sw(r, c4);
                const float4 a  = *(const float4*)(s0 + off);
                const float4 a2 = *(const float4*)(s1 + off);
                const float4 a3 = ((const float4*)gE3)[e4];
                const float4 a4 = *(const float4*)(s2 + off);
                float4 s;
                s.x = fmaf(c13, a.x, fmaf(c14, a2.x, fmaf(c15, a3.x, c16 * a4.x)));
                s.y = fmaf(c13, a.y, fmaf(c14, a2.y, fmaf(c15, a3.y, c16 * a4.y)));
                s.z = fmaf(c13, a.z, fmaf(c14, a2.z, fmaf(c15, a3.z, c16 * a4.z)));
                s.w = fmaf(c13, a.w, fmaf(c14, a2.w, fmaf(c15, a3.w, c16 * a4.w)));
                if ((r >> 2) == c4) ((float*)&s)[r & 3] += c12;
                *(float4*)(s3 + off) = s;
            }
            hbar(m);
        }

        // --- the single GEMM instance ---
        u64 acc[8][4];
#pragma unroll
        for (int i = 0; i < 8; i++) { acc[i][0] = acc[i][1] = acc[i][2] = acc[i][3] = 0ull; }

        float4 av[2][8];
        ulonglong2 bv[2][2];

#define AVLOAD(buf, cc) do {                                                       \
        const int ao_ = (((cc) ^ sA) << 2);                                        \
        _Pragma("unroll")                                                          \
        for (int i_ = 0; i_ < 8; i_++)                                             \
            av[buf][i_] = *(const float4*)(A + ((r0 + i_) << 6) + ao_);            \
    } while (0)

#define BVLOAD(buf, K) do {                                                        \
        const int kr_ = (K) < 63 ? (K) : 63;                                       \
        const int bo_ = ((tx ^ ((kr_ >> 2) & 6)) << 2);                            \
        const float* br_ = B + (kr_ << 6);                                         \
        bv[buf][0] = *(const ulonglong2*)(br_ + bo_);                              \
        bv[buf][1] = *(const ulonglong2*)(br_ + bo_ + 32);                         \
    } while (0)

#define MMCOMP(ab, bb, kk) do {                                                    \
        _Pragma("unroll")                                                          \
        for (int i_ = 0; i_ < 8; i_++) {                                           \
            const float a_ = ((const float*)&av[ab][i_])[kk];                      \
            const u64 aa_ = dup2(a_);                                              \
            acc[i_][0] = fma2(aa_, bv[bb][0].x, acc[i_][0]);                       \
            acc[i_][1] = fma2(aa_, bv[bb][0].y, acc[i_][1]);                       \
            acc[i_][2] = fma2(aa_, bv[bb][1].x, acc[i_][2]);                       \
            acc[i_][3] = fma2(aa_, bv[bb][1].y, acc[i_][3]);                       \
        }                                                                          \
    } while (0)

#define CHUNK(ab, Kbase) do {                                                      \
        BVLOAD(1, (Kbase) + 1); MMCOMP(ab, 0, 0);                                  \
        BVLOAD(0, (Kbase) + 2); MMCOMP(ab, 1, 1);                                  \
        BVLOAD(1, (Kbase) + 3); MMCOMP(ab, 0, 2);                                  \
        BVLOAD(0, (Kbase) + 4); MMCOMP(ab, 1, 3);                                  \
    } while (0)

        AVLOAD(0, 0);
        BVLOAD(0, 0);
#pragma unroll 1
        for (int b = 0; b < 8; b++) {
            const int cc = 2 * b;
            AVLOAD(1, cc + 1);
            CHUNK(0, cc * 4);
            const int nc = (cc + 2 < 15) ? (cc + 2) : 15;
            AVLOAD(0, nc);
            CHUNK(1, (cc + 1) * 4);
        }

#undef AVLOAD
#undef BVLOAD
#undef MMCOMP
#undef CHUNK

        // --- epilogue + store ---
#pragma unroll
        for (int i = 0; i < 8; i++) {
            const int row = r0 + i;
            const int offL = (row << 6) + (sc << 2);
            const int offH = offL + 32;
            const float2 p0 = unpk(acc[i][0]), p1 = unpk(acc[i][1]);
            const float2 p2 = unpk(acc[i][2]), p3 = unpk(acc[i][3]);
            float4 o0 = make_float4(p0.x, p0.y, p1.x, p1.y);
            float4 o1 = make_float4(p2.x, p2.y, p3.x, p3.y);
            if (epi) {
                const float4 e1L = *(const float4*)(gE1 + offL);   // global
                const float4 e2L = *(const float4*)(s1  + offL);   // smem
                const float4 e3L = *(const float4*)(gE3 + offL);   // global
                const float4 e1H = *(const float4*)(gE1 + offH);
                const float4 e2H = *(const float4*)(s1  + offH);
                const float4 e3H = *(const float4*)(gE3 + offH);
                o0.x += fmaf(d1, e1L.x, fmaf(d2, e2L.x, d3 * e3L.x));
                o0.y += fmaf(d1, e1L.y, fmaf(d2, e2L.y, d3 * e3L.y));
                o0.z += fmaf(d1, e1L.z, fmaf(d2, e2L.z, d3 * e3L.z));
                o0.w += fmaf(d1, e1L.w, fmaf(d2, e2L.w, d3 * e3L.w));
                o1.x += fmaf(d1, e1H.x, fmaf(d2, e2H.x, d3 * e3H.x));
                o1.y += fmaf(d1, e1H.y, fmaf(d2, e2H.y, d3 * e3H.y));
                o1.z += fmaf(d1, e1H.z, fmaf(d2, e2H.z, d3 * e3H.z));
                o1.w += fmaf(d1, e1H.w, fmaf(d2, e2H.w, d3 * e3H.w));
                if ((row >> 2) == tx)     ((float*)&o0)[i & 3] += d0;
                if ((row >> 2) == tx + 8) ((float*)&o1)[i & 3] += d0;
            }
            if (toGlobal) {
                *(float4*)(gE3 + offL) = o0;
                *(float4*)(gE3 + offH) = o1;
            } else {
                *(float4*)(C + offL) = o0;
                *(float4*)(C + offH) = o1;
            }
        }
        if (toGlobal) __threadfence_block();
        hbar(m);
    }

    // ---- store (de-swizzle): result in s0 if nsq even, else s3 ----
    const float* src = (nsq & 1) ? s3 : s0;
#pragma unroll
    for (int q = 0; q < 16; q++) {
        const int e4 = t + q * 64;
        const int r = e4 >> 4, c4 = e4 & 15;
        O4[e4] = *(const float4*)(src + sw(r, c4));
    }
}

extern "C" void kernel_launch(void* const* d_in, const int* in_sizes, int n_in,
                              void* d_out, int out_size) {
    const float* R = (const float*)d_in[0];
    const float* G = (const float*)d_in[1];
    float* out = (float*)d_out;

    const int batch = in_sizes[0] / NN;                              // 8192
    const int grid = (batch + MATS_PER_CTA - 1) / MATS_PER_CTA;      // 2731
    const size_t smem = MATS_PER_CTA * 4 * NN * sizeof(float);       // 192 KB

    static bool attr_set = false;
    if (!attr_set) {
        cudaFuncSetAttribute(meg_update_kernel,
                             cudaFuncAttributeMaxDynamicSharedMemorySize,
                             (int)smem);
        attr_set = true;
    }

    meg_update_kernel<<<grid, THREADS, smem>>>(R, G, out, batch);
}

// round 14
// speedup vs baseline: 1.0637x; 1.0134x over previous
#include <cuda_runtime.h>
#include <cuda_bf16.h>
#include <math.h>

#define ETA 0.1f
#define THETA 4.0f
#define NN 4096
#define THREADS 128

typedef unsigned int u32;

// ---- smem float offsets ----
#define F_EA   64
#define F_EA2  (64 + 4096)
#define F_EA3  (64 + 8192)
#define F_S0   (64 + 12288)
#define F_S1   (64 + 16384)
#define F_XH   (64 + 20480)           // u32[2048] bf16x2 A-fragments (high)
#define F_XL   (F_XH + 2048)          // u32[2048] (low)
#define F_YH   (F_XH + 4096)          // u32[2048] B-fragments (high)
#define F_YL   (F_XH + 6144)          // u32[2048] (low)
#define SMEM_FLOATS (64 + 20480 + 8192)   // 28736 floats = 114944 B (2 CTAs/SM)

__device__ __forceinline__ int swi(int r, int c4) {
    return (r << 6) + ((c4 ^ ((r >> 2) & 6)) << 2);
}

__device__ __forceinline__ u32 packbf(float a, float b) {
    __nv_bfloat162 v;
    v.x = __float2bfloat16(a);
    v.y = __float2bfloat16(b);
    return *reinterpret_cast<u32*>(&v);
}
// split (a,b) into bf16 high pair and bf16 residual-low pair
__device__ __forceinline__ void splitpk(float a, float b, u32& hi, u32& lo) {
    __nv_bfloat16 ha = __float2bfloat16(a), hb = __float2bfloat16(b);
    __nv_bfloat162 h; h.x = ha; h.y = hb;
    hi = *reinterpret_cast<u32*>(&h);
    lo = packbf(a - __bfloat162float(ha), b - __bfloat162float(hb));
}

#define MMA(c, a0, a1, a2, a3, b0, b1) \
    asm volatile("mma.sync.aligned.m16n8k16.row.col.f32.bf16.bf16.f32 " \
        "{%0,%1,%2,%3},{%4,%5,%6,%7},{%8,%9},{%0,%1,%2,%3};" \
        : "+f"((c)[0]), "+f"((c)[1]), "+f"((c)[2]), "+f"((c)[3]) \
        : "r"(a0), "r"(a1), "r"(a2), "r"(a3), "r"(b0), "r"(b1))

// B-fragment split-pack: YF slot p <-> element pair (k=2k0,2k0+1 ; n)
__device__ __forceinline__ void ysplit(float* smx, const float* src, int t) {
    u32* YH = (u32*)(smx + F_YH);
    u32* YL = (u32*)(smx + F_YL);
#pragma unroll
    for (int q = 0; q < 16; q++) {
        const int p = t + q * 128;
        const int T = p & 31, b = (p >> 5) & 1, j = (p >> 6) & 7, kk = p >> 9;
        const int g = T >> 2, tg = T & 3;
        const int k = (kk * 8 + b * 4 + tg) * 2;
        const int n = 8 * j + g;
        const int o0 = swi(k, n >> 2) + (n & 3);
        const int o1 = swi(k + 1, n >> 2) + (n & 3);
        u32 hi, lo;
        splitpk(src[o0], src[o1], hi, lo);
        YH[p] = hi; YL[p] = lo;
    }
}
// A-fragment split-pack (initial only)
__device__ __forceinline__ void xsplit(float* smx, const float* src, int t) {
    u32* XH = (u32*)(smx + F_XH);
    u32* XL = (u32*)(smx + F_XL);
#pragma unroll
    for (int q = 0; q < 16; q++) {
        const int p = t + q * 128;
        const int T = p & 31, reg = (p >> 5) & 3, kk = (p >> 7) & 3, w = p >> 9;
        const int r8 = reg & 1, kh = reg >> 1;
        const int row = w * 16 + r8 * 8 + (T >> 2);
        const int k = kk * 16 + kh * 8 + (T & 3) * 2;
        const int off = swi(row, k >> 2) + (k & 3);
        u32 hi, lo;
        splitpk(src[off], src[off + 1], hi, lo);
        XH[p] = hi; XL[p] = lo;
    }
}

__global__ void __launch_bounds__(THREADS, 2)
meg_update_kernel(const float* __restrict__ gR,
                  const float* __restrict__ gG,
                  float* __restrict__ gOut) {
    extern __shared__ float smx[];
    const int t = threadIdx.x;
    const int w = t >> 5, lane = t & 31;
    const int g = lane >> 2, tg = lane & 3;

    float* EA  = smx + F_EA;
    float* EA2 = smx + F_EA2;
    float* EA3 = smx + F_EA3;
    float* S0  = smx + F_S0;
    float* S1  = smx + F_S1;
    u32* XH = (u32*)(smx + F_XH);
    u32* XL = (u32*)(smx + F_XL);
    const u32* YH = (const u32*)(smx + F_YH);
    const u32* YL = (const u32*)(smx + F_YL);

    const size_t gb = (size_t)blockIdx.x * NN;
    const float4* R4 = (const float4*)(gR + gb);
    const float4* G4 = (const float4*)(gG + gb);
    float4* O4 = (float4*)(gOut + gb);

    // ---- G -> S1 (swizzled) ----
#pragma unroll
    for (int q = 0; q < 8; q++) {
        const int e4 = t + q * 128, r = e4 >> 4, c4 = e4 & 15;
        *(float4*)(S1 + swi(r, c4)) = G4[e4];
    }
    __syncthreads();
    // ---- A = log(R) - ETA*(G - G^T) -> EA ----
#pragma unroll
    for (int q = 0; q < 8; q++) {
        const int e4 = t + q * 128, r = e4 >> 4, c4 = e4 & 15, cb = c4 << 2;
        const float4 rv = R4[e4];
        const float4 gv = *(const float4*)(S1 + swi(r, c4));
        const float g0 = S1[swi(cb + 0, r >> 2) + (r & 3)];
        const float g1 = S1[swi(cb + 1, r >> 2) + (r & 3)];
        const float g2 = S1[swi(cb + 2, r >> 2) + (r & 3)];
        const float g3 = S1[swi(cb + 3, r >> 2) + (r & 3)];
        float4 a;
        a.x = logf(rv.x) - ETA * (gv.x - g0);
        a.y = logf(rv.y) - ETA * (gv.y - g1);
        a.z = logf(rv.z) - ETA * (gv.z - g2);
        a.w = logf(rv.w) - ETA * (gv.w - g3);
        *(float4*)(EA + swi(r, c4)) = a;
    }
    __syncthreads();
    // ---- inf-norm -> nsq ----
    if (t < 64) {
        float rs = 0.f;
#pragma unroll
        for (int c = 0; c < 16; c++) {
            const float4 v = *(const float4*)(EA + swi(t, c));
            rs += fabsf(v.x) + fabsf(v.y) + fabsf(v.z) + fabsf(v.w);
        }
#pragma unroll
        for (int o = 16; o > 0; o >>= 1) rs = fmaxf(rs, __shfl_xor_sync(~0u, rs, o));
        if ((t & 31) == 0) smx[4 + (t >> 5)] = rs;
    }
    __syncthreads();
    if (t == 0) {
        const float nrm = fmaxf(smx[4], smx[5]);
        int s = 0;
        if (nrm > THETA && isfinite(nrm)) {
            s = (int)ceilf(log2f(nrm / THETA));
            if (s < 0) s = 0;
            if (s > 30) s = 30;
        }
        ((int*)smx)[6] = s;
    }
    __syncthreads();
    const int nsq = ((int*)smx)[6];
    const float scale = exp2f((float)-nsq);
#pragma unroll
    for (int q = 0; q < 8; q++) {
        float4* p = (float4*)EA + (t + q * 128);
        float4 v = *p; v.x *= scale; v.y *= scale; v.z *= scale; v.w *= scale; *p = v;
    }
    __syncthreads();

    // ---- initial fragments: X = A, Y = A ----
    xsplit(smx, EA, t);
    ysplit(smx, EA, t);
    __syncthreads();

    const float c0 = 1.f, c1 = 1.f, c2 = .5f, c3 = (float)(1.0 / 6.0),
        c4f = (float)(1.0 / 24.0), c5 = (float)(1.0 / 120.0), c6 = (float)(1.0 / 720.0),
        c7 = (float)(1.0 / 5040.0), c8 = (float)(1.0 / 40320.0), c9 = (float)(1.0 / 362880.0),
        c10 = (float)(1.0 / 3628800.0), c11 = (float)(1.0 / 39916800.0),
        c12 = (float)(1.0 / 479001600.0), c13 = (float)(1.0 / 6227020800.0),
        c14 = (float)(1.0 / 87178291200.0), c15 = (float)(1.0 / 1307674368000.0),
        c16 = (float)(1.0 / 20922789888000.0);

    const int nsteps = 6 + nsq;
#pragma unroll 1
    for (int step = 0; step < nsteps; step++) {
        // ---- Y fragment rebuild (steps that change Y) ----
        const float* ysrc = 0;
        if (step == 2) ysrc = EA2;
        else if (step == 3) ysrc = S0;
        else if (step == 4) ysrc = S1;
        else if (step == 5) ysrc = S0;
        else if (step >= 6) ysrc = ((step - 6) & 1) ? S0 : S1;
        if (ysrc) ysplit(smx, ysrc, t);
        __syncthreads();

        // ---- GEMM: 96 HMMA per warp ----
        float acc[8][4];
#pragma unroll
        for (int j = 0; j < 8; j++) { acc[j][0] = acc[j][1] = acc[j][2] = acc[j][3] = 0.f; }

#pragma unroll
        for (int kk = 0; kk < 4; kk++) {
            u32 ah[4], al[4];
#pragma unroll
            for (int r = 0; r < 4; r++) {
                const int ix = (w * 4 + kk) * 128 + r * 32 + lane;
                ah[r] = ((const u32*)(smx + F_XH))[ix];
                al[r] = ((const u32*)(smx + F_XL))[ix];
            }
            u32 bh[8][2], bl[8][2];
#pragma unroll
            for (int j = 0; j < 8; j++) {
                const int ix = kk * 512 + j * 64 + lane;
                bh[j][0] = YH[ix];      bh[j][1] = YH[ix + 32];
                bl[j][0] = YL[ix];      bl[j][1] = YL[ix + 32];
            }
#pragma unroll
            for (int j = 0; j < 8; j++) MMA(acc[j], ah[0], ah[1], ah[2], ah[3], bh[j][0], bh[j][1]);
#pragma unroll
            for (int j = 0; j < 8; j++) MMA(acc[j], al[0], al[1], al[2], al[3], bh[j][0], bh[j][1]);
#pragma unroll
            for (int j = 0; j < 8; j++) MMA(acc[j], ah[0], ah[1], ah[2], ah[3], bl[j][0], bl[j][1]);
        }

        // ---- epilogue selection ----
        float* dst; int mode = 0; int xsp = 0;   // mode: 0 plain, 1 horner, 2 seed
        float d0 = 0.f, d1 = 0.f, d2 = 0.f, d3 = 0.f;
        if (step == 0)      { dst = EA2; xsp = 1; }
        else if (step == 1) { dst = EA3; }
        else if (step == 2) { dst = S0; mode = 2; xsp = 1; }
        else if (step == 3) { dst = S1; mode = 1; d0 = c8;  d1 = c9; d2 = c10; d3 = c11; }
        else if (step == 4) { dst = S0; mode = 1; d0 = c4f; d1 = c5; d2 = c6;  d3 = c7; }
        else if (step == 5) { dst = S1; mode = 1; d0 = c0;  d1 = c1; d2 = c2;  d3 = c3; xsp = 1; }
        else { dst = ((step - 6) & 1) ? S1 : S0; xsp = 1; }

#pragma unroll
        for (int j = 0; j < 8; j++) {
#pragma unroll
            for (int ci = 0; ci < 4; ci++) {
                const int row = 16 * w + g + (ci >> 1) * 8;
                const int col = 8 * j + 2 * tg + (ci & 1);
                const int off = swi(row, col >> 2) + (col & 3);
                float v = acc[j][ci];
                if (mode == 1) {
                    v += fmaf(d1, EA[off], fmaf(d2, EA2[off], d3 * EA3[off]));
                    if (row == col) v += d0;
                } else if (mode == 2) {
                    v = fmaf(c13, EA[off], fmaf(c14, EA2[off], fmaf(c15, EA3[off], c16 * v)));
                    if (row == col) v += c12;
                }
                dst[off] = v;
                // CRITICAL FIX: the X-fragment repack must see the POST-epilogue
                // value (step 5 repacks T, not the raw A4*S product). In seed
                // mode (step 2) keep acc raw: X must become A4 while v holds S.
                if (mode != 2) acc[j][ci] = v;
            }
            if (xsp) {   // repack into next step's A-fragments
                const int ix = ((w * 4 + (j >> 1)) * 4 + (j & 1) * 2) * 32 + lane;
                splitpk(acc[j][0], acc[j][1], XH[ix], XL[ix]);
                splitpk(acc[j][2], acc[j][3], XH[ix + 32], XL[ix + 32]);
            }
        }
        __syncthreads();
    }

    // ---- output ----
    const float* fin = (nsq & 1) ? S0 : S1;
#pragma unroll
    for (int q = 0; q < 8; q++) {
        const int e4 = t + q * 128, r = e4 >> 4, c4 = e4 & 15;
        O4[e4] = *(const float4*)(fin + swi(r, c4));
    }
}

extern "C" void kernel_launch(void* const* d_in, const int* in_sizes, int n_in,
                              void* d_out, int out_size) {
    const float* R = (const float*)d_in[0];
    const float* G = (const float*)d_in[1];
    float* out = (float*)d_out;
    const int batch = in_sizes[0] / NN;
    const size_t smem = (size_t)SMEM_FLOATS * sizeof(float);   // 114944 B

    static bool attr_set = false;
    if (!attr_set) {
        cudaFuncSetAttribute(meg_update_kernel,
                             cudaFuncAttributeMaxDynamicSharedMemorySize, (int)smem);
        attr_set = true;
    }
    meg_update_kernel<<<batch, THREADS, smem>>>(R, G, out);
}

// round 15
// speedup vs baseline: 1.6881x; 1.5870x over previous
#include <cuda_runtime.h>
#include <cuda_bf16.h>
#include <math.h>

#define ETA 0.1f
#define THETA 4.0f
#define NN 4096
#define THREADS 128

typedef unsigned int u32;

// ---- smem float offsets ----
#define F_EA   64
#define F_EA2  (64 + 4096)
#define F_EA3  (64 + 8192)
#define F_S0   (64 + 12288)
#define F_S1   (64 + 16384)
#define F_XH   (64 + 20480)           // u32[2048] bf16x2 A-fragments (high)
#define F_XL   (F_XH + 2048)          // u32[2048] (low)
#define F_YH   (F_XH + 4096)          // u32[2048] B-fragments (high)
#define F_YL   (F_XH + 6144)          // u32[2048] (low)
#define SMEM_FLOATS (64 + 20480 + 8192)   // 28736 floats = 114944 B (2 CTAs/SM)

// per-ROW swizzle xor (was (r>>2)&6): kills the 8-way epilogue and 4-way
// ysplit bank conflicts; pure storage bijection, used consistently everywhere.
__device__ __forceinline__ int swi(int r, int c4) {
    return (r << 6) + ((c4 ^ (r & 7)) << 2);
}

__device__ __forceinline__ u32 packbf(float a, float b) {
    __nv_bfloat162 v;
    v.x = __float2bfloat16(a);
    v.y = __float2bfloat16(b);
    return *reinterpret_cast<u32*>(&v);
}
// split (a,b) into bf16 high pair and bf16 residual-low pair
__device__ __forceinline__ void splitpk(float a, float b, u32& hi, u32& lo) {
    __nv_bfloat16 ha = __float2bfloat16(a), hb = __float2bfloat16(b);
    __nv_bfloat162 h; h.x = ha; h.y = hb;
    hi = *reinterpret_cast<u32*>(&h);
    lo = packbf(a - __bfloat162float(ha), b - __bfloat162float(hb));
}

#define MMA(c, a0, a1, a2, a3, b0, b1) \
    asm volatile("mma.sync.aligned.m16n8k16.row.col.f32.bf16.bf16.f32 " \
        "{%0,%1,%2,%3},{%4,%5,%6,%7},{%8,%9},{%0,%1,%2,%3};" \
        : "+f"((c)[0]), "+f"((c)[1]), "+f"((c)[2]), "+f"((c)[3]) \
        : "r"(a0), "r"(a1), "r"(a2), "r"(a3), "r"(b0), "r"(b1))

// B-fragment split-pack: YF slot p <-> element pair (k=2k0,2k0+1 ; n)
__device__ __forceinline__ void ysplit(float* smx, const float* src, int t) {
    u32* YH = (u32*)(smx + F_YH);
    u32* YL = (u32*)(smx + F_YL);
#pragma unroll
    for (int q = 0; q < 16; q++) {
        const int p = t + q * 128;
        const int T = p & 31, b = (p >> 5) & 1, j = (p >> 6) & 7, kk = p >> 9;
        const int g = T >> 2, tg = T & 3;
        const int k = (kk * 8 + b * 4 + tg) * 2;
        const int n = 8 * j + g;
        const int o0 = swi(k, n >> 2) + (n & 3);
        const int o1 = swi(k + 1, n >> 2) + (n & 3);
        u32 hi, lo;
        splitpk(src[o0], src[o1], hi, lo);
        YH[p] = hi; YL[p] = lo;
    }
}
// A-fragment split-pack (initial only)
__device__ __forceinline__ void xsplit(float* smx, const float* src, int t) {
    u32* XH = (u32*)(smx + F_XH);
    u32* XL = (u32*)(smx + F_XL);
#pragma unroll
    for (int q = 0; q < 16; q++) {
        const int p = t + q * 128;
        const int T = p & 31, reg = (p >> 5) & 3, kk = (p >> 7) & 3, w = p >> 9;
        const int r8 = reg & 1, kh = reg >> 1;
        const int row = w * 16 + r8 * 8 + (T >> 2);
        const int k = kk * 16 + kh * 8 + (T & 3) * 2;
        const int off = swi(row, k >> 2) + (k & 3);
        u32 hi, lo;
        splitpk(src[off], src[off + 1], hi, lo);
        XH[p] = hi; XL[p] = lo;
    }
}

__global__ void __launch_bounds__(THREADS, 2)
meg_update_kernel(const float* __restrict__ gR,
                  const float* __restrict__ gG,
                  float* __restrict__ gOut) {
    extern __shared__ float smx[];
    const int t = threadIdx.x;
    const int w = t >> 5, lane = t & 31;
    const int g = lane >> 2, tg = lane & 3;

    float* EA  = smx + F_EA;
    float* EA2 = smx + F_EA2;
    float* EA3 = smx + F_EA3;
    float* S0  = smx + F_S0;
    float* S1  = smx + F_S1;
    u32* XH = (u32*)(smx + F_XH);
    u32* XL = (u32*)(smx + F_XL);
    const u32* YH = (const u32*)(smx + F_YH);
    const u32* YL = (const u32*)(smx + F_YL);

    const size_t gb = (size_t)blockIdx.x * NN;
    const float4* R4 = (const float4*)(gR + gb);
    const float4* G4 = (const float4*)(gG + gb);
    float4* O4 = (float4*)(gOut + gb);

    // ---- G -> S1 (swizzled) ----
#pragma unroll
    for (int q = 0; q < 8; q++) {
        const int e4 = t + q * 128, r = e4 >> 4, c4 = e4 & 15;
        *(float4*)(S1 + swi(r, c4)) = G4[e4];
    }
    __syncthreads();
    // ---- A = log(R) - ETA*(G - G^T) -> EA ----
#pragma unroll
    for (int q = 0; q < 8; q++) {
        const int e4 = t + q * 128, r = e4 >> 4, c4 = e4 & 15, cb = c4 << 2;
        const float4 rv = R4[e4];
        const float4 gv = *(const float4*)(S1 + swi(r, c4));
        const float g0 = S1[swi(cb + 0, r >> 2) + (r & 3)];
        const float g1 = S1[swi(cb + 1, r >> 2) + (r & 3)];
        const float g2 = S1[swi(cb + 2, r >> 2) + (r & 3)];
        const float g3 = S1[swi(cb + 3, r >> 2) + (r & 3)];
        float4 a;
        a.x = logf(rv.x) - ETA * (gv.x - g0);
        a.y = logf(rv.y) - ETA * (gv.y - g1);
        a.z = logf(rv.z) - ETA * (gv.z - g2);
        a.w = logf(rv.w) - ETA * (gv.w - g3);
        *(float4*)(EA + swi(r, c4)) = a;
    }
    __syncthreads();
    // ---- inf-norm -> nsq ----
    if (t < 64) {
        float rs = 0.f;
#pragma unroll
        for (int c = 0; c < 16; c++) {
            const float4 v = *(const float4*)(EA + swi(t, c));
            rs += fabsf(v.x) + fabsf(v.y) + fabsf(v.z) + fabsf(v.w);
        }
#pragma unroll
        for (int o = 16; o > 0; o >>= 1) rs = fmaxf(rs, __shfl_xor_sync(~0u, rs, o));
        if ((t & 31) == 0) smx[4 + (t >> 5)] = rs;
    }
    __syncthreads();
    if (t == 0) {
        const float nrm = fmaxf(smx[4], smx[5]);
        int s = 0;
        if (nrm > THETA && isfinite(nrm)) {
            s = (int)ceilf(log2f(nrm / THETA));
            if (s < 0) s = 0;
            if (s > 30) s = 30;
        }
        ((int*)smx)[6] = s;
    }
    __syncthreads();
    const int nsq = ((int*)smx)[6];
    const float scale = exp2f((float)-nsq);
#pragma unroll
    for (int q = 0; q < 8; q++) {
        float4* p = (float4*)EA + (t + q * 128);
        float4 v = *p; v.x *= scale; v.y *= scale; v.z *= scale; v.w *= scale; *p = v;
    }
    __syncthreads();

    // ---- initial fragments: X = A, Y = A ----
    xsplit(smx, EA, t);
    ysplit(smx, EA, t);
    __syncthreads();

    const float c0 = 1.f, c1 = 1.f, c2 = .5f, c3 = (float)(1.0 / 6.0),
        c4f = (float)(1.0 / 24.0), c5 = (float)(1.0 / 120.0), c6 = (float)(1.0 / 720.0),
        c7 = (float)(1.0 / 5040.0), c8 = (float)(1.0 / 40320.0), c9 = (float)(1.0 / 362880.0),
        c10 = (float)(1.0 / 3628800.0), c11 = (float)(1.0 / 39916800.0),
        c12 = (float)(1.0 / 479001600.0), c13 = (float)(1.0 / 6227020800.0),
        c14 = (float)(1.0 / 87178291200.0), c15 = (float)(1.0 / 1307674368000.0),
        c16 = (float)(1.0 / 20922789888000.0);

    const int nsteps = 6 + nsq;
#pragma unroll 1
    for (int step = 0; step < nsteps; step++) {
        // ---- Y fragment rebuild (steps that change Y) ----
        const float* ysrc = 0;
        if (step == 2) ysrc = EA2;
        else if (step == 3) ysrc = S0;
        else if (step == 4) ysrc = S1;
        else if (step == 5) ysrc = S0;
        else if (step >= 6) ysrc = ((step - 6) & 1) ? S0 : S1;
        if (ysrc) ysplit(smx, ysrc, t);
        __syncthreads();

        // ---- GEMM: 96 HMMA per warp ----
        float acc[8][4];
#pragma unroll
        for (int j = 0; j < 8; j++) { acc[j][0] = acc[j][1] = acc[j][2] = acc[j][3] = 0.f; }

#pragma unroll
        for (int kk = 0; kk < 4; kk++) {
            u32 ah[4], al[4];
#pragma unroll
            for (int r = 0; r < 4; r++) {
                const int ix = (w * 4 + kk) * 128 + r * 32 + lane;
                ah[r] = ((const u32*)(smx + F_XH))[ix];
                al[r] = ((const u32*)(smx + F_XL))[ix];
            }
            u32 bh[8][2], bl[8][2];
#pragma unroll
            for (int j = 0; j < 8; j++) {
                const int ix = kk * 512 + j * 64 + lane;
                bh[j][0] = YH[ix];      bh[j][1] = YH[ix + 32];
                bl[j][0] = YL[ix];      bl[j][1] = YL[ix + 32];
            }
#pragma unroll
            for (int j = 0; j < 8; j++) MMA(acc[j], ah[0], ah[1], ah[2], ah[3], bh[j][0], bh[j][1]);
#pragma unroll
            for (int j = 0; j < 8; j++) MMA(acc[j], al[0], al[1], al[2], al[3], bh[j][0], bh[j][1]);
#pragma unroll
            for (int j = 0; j < 8; j++) MMA(acc[j], ah[0], ah[1], ah[2], ah[3], bl[j][0], bl[j][1]);
        }

        // ---- epilogue selection ----
        float* dst; int mode = 0; int xsp = 0;   // mode: 0 plain, 1 horner, 2 seed
        float d0 = 0.f, d1 = 0.f, d2 = 0.f, d3 = 0.f;
        if (step == 0)      { dst = EA2; xsp = 1; }
        else if (step == 1) { dst = EA3; }
        else if (step == 2) { dst = S0; mode = 2; xsp = 1; }
        else if (step == 3) { dst = S1; mode = 1; d0 = c8;  d1 = c9; d2 = c10; d3 = c11; }
        else if (step == 4) { dst = S0; mode = 1; d0 = c4f; d1 = c5; d2 = c6;  d3 = c7; }
        else if (step == 5) { dst = S1; mode = 1; d0 = c0;  d1 = c1; d2 = c2;  d3 = c3; xsp = 1; }
        else { dst = ((step - 6) & 1) ? S1 : S0; xsp = 1; }

#pragma unroll
        for (int j = 0; j < 8; j++) {
#pragma unroll
            for (int ch = 0; ch < 2; ch++) {        // ci = 2*ch + {0,1}: adjacent cols
                const int row = 16 * w + g + ch * 8;
                const int col = 8 * j + 2 * tg;     // even -> float2-aligned
                const int off = swi(row, col >> 2) + (col & 3);
                float vx = acc[j][2 * ch + 0];
                float vy = acc[j][2 * ch + 1];
                if (mode == 1) {
                    const float2 e1 = *(const float2*)(EA  + off);
                    const float2 e2 = *(const float2*)(EA2 + off);
                    const float2 e3 = *(const float2*)(EA3 + off);
                    vx += fmaf(d1, e1.x, fmaf(d2, e2.x, d3 * e3.x));
                    vy += fmaf(d1, e1.y, fmaf(d2, e2.y, d3 * e3.y));
                    if (row == col)     vx += d0;
                    if (row == col + 1) vy += d0;
                } else if (mode == 2) {
                    const float2 e1 = *(const float2*)(EA  + off);
                    const float2 e2 = *(const float2*)(EA2 + off);
                    const float2 e3 = *(const float2*)(EA3 + off);
                    vx = fmaf(c13, e1.x, fmaf(c14, e2.x, fmaf(c15, e3.x, c16 * vx)));
                    vy = fmaf(c13, e1.y, fmaf(c14, e2.y, fmaf(c15, e3.y, c16 * vy)));
                    if (row == col)     vx += c12;
                    if (row == col + 1) vy += c12;
                }
                *(float2*)(dst + off) = make_float2(vx, vy);
                // repack must see POST-epilogue values except in seed mode
                // (step 2: X must become A4 while vx/vy hold the seed S).
                if (mode != 2) { acc[j][2 * ch + 0] = vx; acc[j][2 * ch + 1] = vy; }
            }
            if (xsp) {   // repack into next step's A-fragments
                const int ix = ((w * 4 + (j >> 1)) * 4 + (j & 1) * 2) * 32 + lane;
                splitpk(acc[j][0], acc[j][1], XH[ix], XL[ix]);
                splitpk(acc[j][2], acc[j][3], XH[ix + 32], XL[ix + 32]);
            }
        }
        __syncthreads();
    }

    // ---- output ----
    const float* fin = (nsq & 1) ? S0 : S1;
#pragma unroll
    for (int q = 0; q < 8; q++) {
        const int e4 = t + q * 128, r = e4 >> 4, c4 = e4 & 15;
        O4[e4] = *(const float4*)(fin + swi(r, c4));
    }
}

extern "C" void kernel_launch(void* const* d_in, const int* in_sizes, int n_in,
                              void* d_out, int out_size) {
    const float* R = (const float*)d_in[0];
    const float* G = (const float*)d_in[1];
    float* out = (float*)d_out;
    const int batch = in_sizes[0] / NN;
    const size_t smem = (size_t)SMEM_FLOATS * sizeof(float);   // 114944 B

    static bool attr_set = false;
    if (!attr_set) {
        cudaFuncSetAttribute(meg_update_kernel,
                             cudaFuncAttributeMaxDynamicSharedMemorySize, (int)smem);
        attr_set = true;
    }
    meg_update_kernel<<<batch, THREADS, smem>>>(R, G, out);
}